// round 3
// baseline (speedup 1.0000x reference)
#include <cuda_runtime.h>
#include <math.h>

#define C_DIM 512
#define HW    4096
#define BATCH 2
#define CPG   16   // channels per group (512/32)

// ---- scratch (static device globals: allocation-free per harness rules) ----
__device__ float g_h  [BATCH * HW * C_DIM];          // groupnorm output, token-major (t, c)
__device__ float g_q  [BATCH * HW * C_DIM];          // (t, c)
__device__ float g_k  [BATCH * HW * C_DIM];          // (t, c)
__device__ float g_vt [C_DIM * BATCH * HW];          // V transposed: (c, t_global)
__device__ float g_att[BATCH * HW * C_DIM];          // attention output, (t, c)
__device__ float g_sc [(size_t)BATCH * HW * HW];     // scores (b, t, s)  ~134 MB

// ============================================================================
// GroupNorm + transpose to token-major.
// grid = B*32 blocks (one per (b, group)), 256 threads.
// ============================================================================
__global__ void gn_transpose(const float* __restrict__ x,
                             const float* __restrict__ gw,
                             const float* __restrict__ gb,
                             float* __restrict__ h)
{
    const int b = blockIdx.x >> 5;
    const int g = blockIdx.x & 31;
    const float* xp = x + ((size_t)b * C_DIM + (size_t)g * CPG) * HW;

    float s = 0.f, sq = 0.f;
    for (int i = threadIdx.x; i < CPG * HW; i += 256) {
        float v = xp[i];
        s += v; sq += v * v;
    }
    __shared__ float reds[8], redq[8];
    #pragma unroll
    for (int o = 16; o > 0; o >>= 1) {
        s  += __shfl_xor_sync(0xffffffffu, s,  o);
        sq += __shfl_xor_sync(0xffffffffu, sq, o);
    }
    if ((threadIdx.x & 31) == 0) { reds[threadIdx.x >> 5] = s; redq[threadIdx.x >> 5] = sq; }
    __syncthreads();
    float ts = 0.f, tq = 0.f;
    #pragma unroll
    for (int w = 0; w < 8; w++) { ts += reds[w]; tq += redq[w]; }

    const float mean = ts * (1.f / 65536.f);
    float var = tq * (1.f / 65536.f) - mean * mean;
    var = var < 0.f ? 0.f : var;
    const float istd = rsqrtf(var + 1e-6f);

    float wv[CPG], bv[CPG];
    #pragma unroll
    for (int c = 0; c < CPG; c++) {
        float w = gw[g * CPG + c];
        wv[c] = w * istd;
        bv[c] = gb[g * CPG + c] - mean * istd * w;
    }

    for (int t = threadIdx.x; t < HW; t += 256) {
        float o[CPG];
        #pragma unroll
        for (int c = 0; c < CPG; c++)
            o[c] = xp[(size_t)c * HW + t] * wv[c] + bv[c];
        float4* dst = (float4*)(h + ((size_t)(b * HW + t)) * C_DIM + g * CPG);
        dst[0] = make_float4(o[0],  o[1],  o[2],  o[3]);
        dst[1] = make_float4(o[4],  o[5],  o[6],  o[7]);
        dst[2] = make_float4(o[8],  o[9],  o[10], o[11]);
        dst[3] = make_float4(o[12], o[13], o[14], o[15]);
    }
}

// ============================================================================
// Generic NT SGEMM: C[m,n] = alpha * sum_k A[m,k]*B[n,k] + bias_m[m] + bias_n[n] + resid[m,n]
// Block tile 128x128, K-step 16, 256 threads, 8x8 per-thread, double-buffered smem.
// Grid: (N/128, M/128). All problem dims here are multiples of 128 (K mult of 16).
// ============================================================================
__global__ __launch_bounds__(256, 2)
void sgemm_nt(const float* __restrict__ A, int lda,
              const float* __restrict__ B, int ldb,
              float* __restrict__ Co, int ldc,
              int K, float alpha,
              const float* __restrict__ bias_m,
              const float* __restrict__ bias_n,
              const float* __restrict__ resid)
{
    __shared__ float As[2][16][132];
    __shared__ float Bs[2][16][132];

    const int tid  = threadIdx.x;
    const int bm   = blockIdx.y * 128;
    const int bn   = blockIdx.x * 128;
    const int lrow = tid >> 2;          // 0..63
    const int lcol = (tid & 3) << 2;    // 0,4,8,12

    const float* Ag = A + (size_t)(bm + lrow) * lda + lcol;
    const float* Bg = B + (size_t)(bn + lrow) * ldb + lcol;

    const int tx = tid & 15;            // n-tile index
    const int ty = tid >> 4;            // m-tile index

    float acc[8][8];
    #pragma unroll
    for (int i = 0; i < 8; i++)
        #pragma unroll
        for (int j = 0; j < 8; j++) acc[i][j] = 0.f;

    float4 pa0, pa1, pb0, pb1;

    // preload tile 0
    pa0 = *(const float4*)(Ag);
    pa1 = *(const float4*)(Ag + (size_t)64 * lda);
    pb0 = *(const float4*)(Bg);
    pb1 = *(const float4*)(Bg + (size_t)64 * ldb);
    As[0][lcol + 0][lrow]      = pa0.x; As[0][lcol + 1][lrow]      = pa0.y;
    As[0][lcol + 2][lrow]      = pa0.z; As[0][lcol + 3][lrow]      = pa0.w;
    As[0][lcol + 0][lrow + 64] = pa1.x; As[0][lcol + 1][lrow + 64] = pa1.y;
    As[0][lcol + 2][lrow + 64] = pa1.z; As[0][lcol + 3][lrow + 64] = pa1.w;
    Bs[0][lcol + 0][lrow]      = pb0.x; Bs[0][lcol + 1][lrow]      = pb0.y;
    Bs[0][lcol + 2][lrow]      = pb0.z; Bs[0][lcol + 3][lrow]      = pb0.w;
    Bs[0][lcol + 0][lrow + 64] = pb1.x; Bs[0][lcol + 1][lrow + 64] = pb1.y;
    Bs[0][lcol + 2][lrow + 64] = pb1.z; Bs[0][lcol + 3][lrow + 64] = pb1.w;
    __syncthreads();

    const int KT = K >> 4;
    for (int kt = 0; kt < KT; kt++) {
        const int cur = kt & 1;
        if (kt + 1 < KT) {
            const int k0 = (kt + 1) << 4;
            pa0 = *(const float4*)(Ag + k0);
            pa1 = *(const float4*)(Ag + (size_t)64 * lda + k0);
            pb0 = *(const float4*)(Bg + k0);
            pb1 = *(const float4*)(Bg + (size_t)64 * ldb + k0);
        }
        #pragma unroll
        for (int kk = 0; kk < 16; kk++) {
            float a[8], bb[8];
            *(float4*)&a[0]  = *(const float4*)&As[cur][kk][ty * 8];
            *(float4*)&a[4]  = *(const float4*)&As[cur][kk][ty * 8 + 4];
            *(float4*)&bb[0] = *(const float4*)&Bs[cur][kk][tx * 8];
            *(float4*)&bb[4] = *(const float4*)&Bs[cur][kk][tx * 8 + 4];
            #pragma unroll
            for (int i = 0; i < 8; i++)
                #pragma unroll
                for (int j = 0; j < 8; j++)
                    acc[i][j] += a[i] * bb[j];
        }
        if (kt + 1 < KT) {
            const int nxt = cur ^ 1;
            As[nxt][lcol + 0][lrow]      = pa0.x; As[nxt][lcol + 1][lrow]      = pa0.y;
            As[nxt][lcol + 2][lrow]      = pa0.z; As[nxt][lcol + 3][lrow]      = pa0.w;
            As[nxt][lcol + 0][lrow + 64] = pa1.x; As[nxt][lcol + 1][lrow + 64] = pa1.y;
            As[nxt][lcol + 2][lrow + 64] = pa1.z; As[nxt][lcol + 3][lrow + 64] = pa1.w;
            Bs[nxt][lcol + 0][lrow]      = pb0.x; Bs[nxt][lcol + 1][lrow]      = pb0.y;
            Bs[nxt][lcol + 2][lrow]      = pb0.z; Bs[nxt][lcol + 3][lrow]      = pb0.w;
            Bs[nxt][lcol + 0][lrow + 64] = pb1.x; Bs[nxt][lcol + 1][lrow + 64] = pb1.y;
            Bs[nxt][lcol + 2][lrow + 64] = pb1.z; Bs[nxt][lcol + 3][lrow + 64] = pb1.w;
            __syncthreads();
        }
    }

    // epilogue
    float bnv[8];
    #pragma unroll
    for (int j = 0; j < 8; j++)
        bnv[j] = bias_n ? bias_n[bn + tx * 8 + j] : 0.f;

    #pragma unroll
    for (int i = 0; i < 8; i++) {
        const int m = bm + ty * 8 + i;
        const float bmv = bias_m ? bias_m[m] : 0.f;
        float* crow = Co + (size_t)m * ldc + bn + tx * 8;
        float o[8];
        #pragma unroll
        for (int j = 0; j < 8; j++) o[j] = acc[i][j] * alpha + bmv + bnv[j];
        if (resid) {
            const float* rrow = resid + (size_t)m * ldc + bn + tx * 8;
            #pragma unroll
            for (int j = 0; j < 8; j++) o[j] += rrow[j];
        }
        *(float4*)(crow)     = make_float4(o[0], o[1], o[2], o[3]);
        *(float4*)(crow + 4) = make_float4(o[4], o[5], o[6], o[7]);
    }
}

// ============================================================================
// Row softmax over rows of length 4096 (in place). grid = 8192, 256 threads.
// Whole row lives in registers (16 floats/thread).
// ============================================================================
__global__ void softmax4096(float* __restrict__ S)
{
    float4* row = (float4*)(S + (size_t)blockIdx.x * 4096);
    const int tid = threadIdx.x;
    float4 v[4];
    float mx = -1e30f;
    #pragma unroll
    for (int i = 0; i < 4; i++) {
        v[i] = row[i * 256 + tid];
        mx = fmaxf(mx, fmaxf(fmaxf(v[i].x, v[i].y), fmaxf(v[i].z, v[i].w)));
    }
    __shared__ float red[8];
    #pragma unroll
    for (int o = 16; o > 0; o >>= 1) mx = fmaxf(mx, __shfl_xor_sync(0xffffffffu, mx, o));
    if ((tid & 31) == 0) red[tid >> 5] = mx;
    __syncthreads();
    mx = red[0];
    #pragma unroll
    for (int w = 1; w < 8; w++) mx = fmaxf(mx, red[w]);

    float sum = 0.f;
    #pragma unroll
    for (int i = 0; i < 4; i++) {
        v[i].x = __expf(v[i].x - mx); v[i].y = __expf(v[i].y - mx);
        v[i].z = __expf(v[i].z - mx); v[i].w = __expf(v[i].w - mx);
        sum += v[i].x + v[i].y + v[i].z + v[i].w;
    }
    __syncthreads();  // protect red[] reuse
    #pragma unroll
    for (int o = 16; o > 0; o >>= 1) sum += __shfl_xor_sync(0xffffffffu, sum, o);
    if ((tid & 31) == 0) red[tid >> 5] = sum;
    __syncthreads();
    sum = 0.f;
    #pragma unroll
    for (int w = 0; w < 8; w++) sum += red[w];
    const float inv = __frcp_rn(sum);
    #pragma unroll
    for (int i = 0; i < 4; i++) {
        v[i].x *= inv; v[i].y *= inv; v[i].z *= inv; v[i].w *= inv;
        row[i * 256 + tid] = v[i];
    }
}

// ============================================================================
extern "C" void kernel_launch(void* const* d_in, const int* in_sizes, int n_in,
                              void* d_out, int out_size)
{
    const float* x   = (const float*)d_in[0];
    const float* gnw = (const float*)d_in[1];
    const float* gnb = (const float*)d_in[2];
    const float* qw  = (const float*)d_in[3];
    const float* qb  = (const float*)d_in[4];
    const float* kw  = (const float*)d_in[5];
    const float* kb  = (const float*)d_in[6];
    const float* vw  = (const float*)d_in[7];
    const float* vb  = (const float*)d_in[8];
    const float* pw  = (const float*)d_in[9];
    const float* pb  = (const float*)d_in[10];
    float* out = (float*)d_out;

    float *h, *q, *k, *vt, *att, *sc;
    cudaGetSymbolAddress((void**)&h,   g_h);
    cudaGetSymbolAddress((void**)&q,   g_q);
    cudaGetSymbolAddress((void**)&k,   g_k);
    cudaGetSymbolAddress((void**)&vt,  g_vt);
    cudaGetSymbolAddress((void**)&att, g_att);
    cudaGetSymbolAddress((void**)&sc,  g_sc);

    // 1. GroupNorm + transpose to (t, c)
    gn_transpose<<<64, 256>>>(x, gnw, gnb, h);

    // 2. Q, K: (8192 x 512) = h @ W^T + b   (token-major outputs)
    sgemm_nt<<<dim3(4, 64), 256>>>(h, 512, qw, 512, q, 512, 512, 1.f, nullptr, qb, nullptr);
    sgemm_nt<<<dim3(4, 64), 256>>>(h, 512, kw, 512, k, 512, 512, 1.f, nullptr, kb, nullptr);

    // 3. Vt: (512 x 8192) = W_v @ h^T + b   (channel-major so PV GEMM is NT)
    sgemm_nt<<<dim3(64, 4), 256>>>(vw, 512, h, 512, vt, 8192, 512, 1.f, vb, nullptr, nullptr);

    // 4. scores[b] = (q_b @ k_b^T) / sqrt(C)
    const float scale = 0.044194173824159216f;  // 1/sqrt(512)
    for (int b = 0; b < 2; b++) {
        sgemm_nt<<<dim3(32, 32), 256>>>(q + (size_t)b * HW * C_DIM, 512,
                                        k + (size_t)b * HW * C_DIM, 512,
                                        sc + (size_t)b * HW * HW, 4096,
                                        512, scale, nullptr, nullptr, nullptr);
    }

    // 5. softmax over all 8192 rows
    softmax4096<<<8192, 256>>>(sc);

    // 6. att[b] = P_b @ V_b   (B operand = vt slice, ldb = 8192)
    for (int b = 0; b < 2; b++) {
        sgemm_nt<<<dim3(4, 32), 256>>>(sc + (size_t)b * HW * HW, 4096,
                                       vt + (size_t)b * HW, 8192,
                                       att + (size_t)b * HW * C_DIM, 512,
                                       4096, 1.f, nullptr, nullptr, nullptr);
    }

    // 7. out[b] = W_p @ att_b^T + p_b + x_b   (directly in (B,C,H,W) layout)
    for (int b = 0; b < 2; b++) {
        sgemm_nt<<<dim3(32, 4), 256>>>(pw, 512,
                                       att + (size_t)b * HW * C_DIM, 512,
                                       out + (size_t)b * C_DIM * HW, 4096,
                                       512, 1.f, pb, nullptr,
                                       x + (size_t)b * C_DIM * HW);
    }
}

// round 10
// speedup vs baseline: 2.3461x; 2.3461x over previous
#include <cuda_runtime.h>
#include <cuda_bf16.h>
#include <stdint.h>
#include <math.h>

using bf16 = __nv_bfloat16;

#define C_DIM 512
#define HW    4096
#define BATCH 2
#define CPG   16

// ---------------------------------------------------------------------------
// scratch (__device__ globals; allocation-free per harness rules)
// ---------------------------------------------------------------------------
#define TOK (BATCH * HW)             // 8192 tokens
__device__ bf16 g_hh[TOK * C_DIM],  g_hl[TOK * C_DIM];     // groupnorm out, (t,c) split
__device__ bf16 g_qh[TOK * C_DIM],  g_ql[TOK * C_DIM];
__device__ bf16 g_kh[TOK * C_DIM],  g_kl[TOK * C_DIM];
__device__ bf16 g_vth[C_DIM * TOK], g_vtl[C_DIM * TOK];    // V transposed (c, t_global)
__device__ bf16 g_ah[TOK * C_DIM],  g_al[TOK * C_DIM];     // attention out (t,c) split
__device__ bf16 g_wqh[C_DIM*C_DIM], g_wql[C_DIM*C_DIM];
__device__ bf16 g_wkh[C_DIM*C_DIM], g_wkl[C_DIM*C_DIM];
__device__ bf16 g_wvh[C_DIM*C_DIM], g_wvl[C_DIM*C_DIM];
__device__ bf16 g_wph[C_DIM*C_DIM], g_wpl[C_DIM*C_DIM];
__device__ float g_sc[(size_t)BATCH * HW * HW];            // scores fp32 (134 MB)
__device__ bf16 g_ph[(size_t)BATCH * HW * HW];             // softmax probs split
__device__ bf16 g_pl[(size_t)BATCH * HW * HW];

// ---------------------------------------------------------------------------
// helpers
// ---------------------------------------------------------------------------
__device__ __forceinline__ uint32_t smem_u32(const void* p) {
    uint32_t a;
    asm("{ .reg .u64 t; cvta.to.shared.u64 t, %1; cvt.u32.u64 %0, t; }" : "=r"(a) : "l"(p));
    return a;
}
__device__ __forceinline__ void ldsm4(uint32_t* r, uint32_t addr) {
    asm volatile("ldmatrix.sync.aligned.m8n8.x4.shared.b16 {%0,%1,%2,%3}, [%4];"
                 : "=r"(r[0]), "=r"(r[1]), "=r"(r[2]), "=r"(r[3]) : "r"(addr));
}
__device__ __forceinline__ void mma_bf16(float* d, const uint32_t* a, const uint32_t* b) {
    asm volatile("mma.sync.aligned.m16n8k16.row.col.f32.bf16.bf16.f32 "
                 "{%0,%1,%2,%3}, {%4,%5,%6,%7}, {%8,%9}, {%0,%1,%2,%3};"
                 : "+f"(d[0]), "+f"(d[1]), "+f"(d[2]), "+f"(d[3])
                 : "r"(a[0]), "r"(a[1]), "r"(a[2]), "r"(a[3]), "r"(b[0]), "r"(b[1]));
}
__device__ __forceinline__ void split2(float v, bf16& h, bf16& l) {
    h = __float2bfloat16_rn(v);
    l = __float2bfloat16_rn(v - __bfloat162float(h));
}

// ---------------------------------------------------------------------------
// GroupNorm + transpose + bf16 hi/lo split.  grid = 64, 256 thr.
// ---------------------------------------------------------------------------
__global__ void gn_transpose(const float* __restrict__ x,
                             const float* __restrict__ gw,
                             const float* __restrict__ gb,
                             bf16* __restrict__ hh, bf16* __restrict__ hl)
{
    const int b = blockIdx.x >> 5;
    const int g = blockIdx.x & 31;
    const float* xp = x + ((size_t)b * C_DIM + (size_t)g * CPG) * HW;

    float s = 0.f, sq = 0.f;
    for (int i = threadIdx.x; i < CPG * HW; i += 256) {
        float v = xp[i];
        s += v; sq += v * v;
    }
    __shared__ float reds[8], redq[8];
    #pragma unroll
    for (int o = 16; o > 0; o >>= 1) {
        s  += __shfl_xor_sync(0xffffffffu, s,  o);
        sq += __shfl_xor_sync(0xffffffffu, sq, o);
    }
    if ((threadIdx.x & 31) == 0) { reds[threadIdx.x >> 5] = s; redq[threadIdx.x >> 5] = sq; }
    __syncthreads();
    float ts = 0.f, tq = 0.f;
    #pragma unroll
    for (int w = 0; w < 8; w++) { ts += reds[w]; tq += redq[w]; }

    const float mean = ts * (1.f / 65536.f);
    float var = tq * (1.f / 65536.f) - mean * mean;
    var = var < 0.f ? 0.f : var;
    const float istd = rsqrtf(var + 1e-6f);

    float wv[CPG], bv[CPG];
    #pragma unroll
    for (int c = 0; c < CPG; c++) {
        float w = gw[g * CPG + c];
        wv[c] = w * istd;
        bv[c] = gb[g * CPG + c] - mean * istd * w;
    }
    for (int t = threadIdx.x; t < HW; t += 256) {
        float o[CPG];
        #pragma unroll
        for (int c = 0; c < CPG; c++)
            o[c] = xp[(size_t)c * HW + t] * wv[c] + bv[c];
        size_t base = (size_t)(b * HW + t) * C_DIM + g * CPG;
        __nv_bfloat162* dh = (__nv_bfloat162*)(hh + base);
        __nv_bfloat162* dl = (__nv_bfloat162*)(hl + base);
        #pragma unroll
        for (int j = 0; j < 8; j++) {
            bf16 h0, l0, h1, l1;
            split2(o[2*j],   h0, l0);
            split2(o[2*j+1], h1, l1);
            dh[j] = __halves2bfloat162(h0, h1);
            dl[j] = __halves2bfloat162(l0, l1);
        }
    }
}

// ---------------------------------------------------------------------------
// fp32 -> bf16 hi/lo split of a flat array (weights).
// ---------------------------------------------------------------------------
__global__ void split_arr(const float* __restrict__ w, bf16* __restrict__ hi,
                          bf16* __restrict__ lo, int n)
{
    int i = blockIdx.x * 256 + threadIdx.x;
    if (i < n) {
        bf16 h, l;
        split2(w[i], h, l);
        hi[i] = h; lo[i] = l;
    }
}

// ---------------------------------------------------------------------------
// bf16-split NT GEMM on mma.sync tensor cores (sm_80+ PTX, works on sm_103).
// C[m,n] = (sum_k A[m,k]B[n,k] + bias_m[m] + bias_n[n]) * alpha + resid[m,n]
// A,B as hi/lo bf16 pairs; 3 MMA products (hh, hl, lh) per logical product.
// Block tile 128x128, BK=32, 256 thr (8 warps, 2x4), 64x32 per warp.
// Software-pipelined gmem->reg->smem double buffer. smem row stride 80 B.
// ---------------------------------------------------------------------------
#define ROWB      80                      // smem row stride (32 bf16 = 64 B data + 16 pad)
#define TILE_B    (128 * ROWB)            // 10240 per tile
#define STG_B     (4 * TILE_B)            // Ah, Al, Bh, Bl
#define TG_SMEM   (2 * STG_B)             // 81920

__global__ __launch_bounds__(256, 1)
void tgemm(const bf16* __restrict__ Ahi, const bf16* __restrict__ Alo, int lda,
           const bf16* __restrict__ Bhi, const bf16* __restrict__ Blo, int ldb,
           int K, float alpha,
           const float* __restrict__ bias_m, const float* __restrict__ bias_n,
           const float* __restrict__ resid,
           float* __restrict__ outF, bf16* __restrict__ Chi, bf16* __restrict__ Clo,
           int ldc)
{
    extern __shared__ __align__(128) char smem[];
    const uint32_t sb = smem_u32(smem);
    const int tid = threadIdx.x, lane = tid & 31, wid = tid >> 5;
    const int bm = blockIdx.y * 128, bn = blockIdx.x * 128;
    const int wm = wid >> 2, wn = wid & 3;            // 2x4 warp grid

    // per-thread load coords: rows r0/r0+64, 16B chunk c0 (covers 128 rows x 32 k)
    const int r0 = tid >> 2, c0 = tid & 3;

    float acc[4][4][4];
    #pragma unroll
    for (int i = 0; i < 4; i++)
        #pragma unroll
        for (int j = 0; j < 4; j++)
            #pragma unroll
            for (int e = 0; e < 4; e++) acc[i][j][e] = 0.f;

    uint4 v[8];
    auto gload = [&](int kt) {
        const int k0 = kt * 32 + c0 * 8;
        const size_t a0 = (size_t)(bm + r0) * lda + k0;
        const size_t b0 = (size_t)(bn + r0) * ldb + k0;
        v[0] = *(const uint4*)(Ahi + a0);
        v[1] = *(const uint4*)(Alo + a0);
        v[2] = *(const uint4*)(Bhi + b0);
        v[3] = *(const uint4*)(Blo + b0);
        const size_t a1 = a0 + (size_t)64 * lda;
        const size_t b1 = b0 + (size_t)64 * ldb;
        v[4] = *(const uint4*)(Ahi + a1);
        v[5] = *(const uint4*)(Alo + a1);
        v[6] = *(const uint4*)(Bhi + b1);
        v[7] = *(const uint4*)(Blo + b1);
    };
    auto sstore = [&](int s) {
        char* st = smem + s * STG_B;
        const uint32_t o0 = r0 * ROWB + c0 * 16;
        const uint32_t o1 = o0 + 64 * ROWB;
        *(uint4*)(st + o0)              = v[0];
        *(uint4*)(st + TILE_B + o0)     = v[1];
        *(uint4*)(st + 2 * TILE_B + o0) = v[2];
        *(uint4*)(st + 3 * TILE_B + o0) = v[3];
        *(uint4*)(st + o1)              = v[4];
        *(uint4*)(st + TILE_B + o1)     = v[5];
        *(uint4*)(st + 2 * TILE_B + o1) = v[6];
        *(uint4*)(st + 3 * TILE_B + o1) = v[7];
    };

    // ldmatrix lane addressing (x4 = four 8x8 tiles; group g = lane>>3)
    const int g = lane >> 3;
    const int arow = wm * 64 + (g & 1) * 8 + (lane & 7);   // + i*16
    const uint32_t acol = (uint32_t)((g >> 1) * 16);        // + ks*32
    const int brow = wn * 32 + (g >> 1) * 8 + (lane & 7);   // + jp*16
    const uint32_t bcol = (uint32_t)((g & 1) * 16);         // + ks*32

    auto compute = [&](int s) {
        const uint32_t stg = sb + s * STG_B;
        #pragma unroll
        for (int ks = 0; ks < 2; ks++) {
            uint32_t ah[4][4], al[4][4], bh[2][4], bl[2][4];
            #pragma unroll
            for (int i = 0; i < 4; i++) {
                const uint32_t ad = stg + (uint32_t)(arow + i * 16) * ROWB + acol + ks * 32;
                ldsm4(ah[i], ad);
                ldsm4(al[i], ad + TILE_B);
            }
            #pragma unroll
            for (int jp = 0; jp < 2; jp++) {
                const uint32_t bd = stg + 2 * TILE_B +
                                    (uint32_t)(brow + jp * 16) * ROWB + bcol + ks * 32;
                ldsm4(bh[jp], bd);
                ldsm4(bl[jp], bd + TILE_B);
            }
            #pragma unroll
            for (int i = 0; i < 4; i++)
                #pragma unroll
                for (int j = 0; j < 4; j++) {
                    const uint32_t* bhj = &bh[j >> 1][(j & 1) * 2];
                    const uint32_t* blj = &bl[j >> 1][(j & 1) * 2];
                    mma_bf16(acc[i][j], ah[i], bhj);   // hi * hi
                    mma_bf16(acc[i][j], al[i], bhj);   // lo * hi
                    mma_bf16(acc[i][j], ah[i], blj);   // hi * lo
                }
        }
    };

    const int KT = K >> 5;   // chunks of 32
    gload(0); sstore(0);
    __syncthreads();
    for (int kt = 0; kt < KT; kt++) {
        if (kt + 1 < KT) gload(kt + 1);
        compute(kt & 1);
        if (kt + 1 < KT) {
            sstore((kt + 1) & 1);
            __syncthreads();
        }
    }

    // ---- epilogue ----
    const int er = lane >> 2;          // 0..7
    const int ec = (lane & 3) * 2;
    #pragma unroll
    for (int i = 0; i < 4; i++) {
        const int m0 = bm + wm * 64 + i * 16 + er;   // rows m0, m0+8
        const float bm0 = bias_m ? bias_m[m0] : 0.f;
        const float bm1 = bias_m ? bias_m[m0 + 8] : 0.f;
        #pragma unroll
        for (int j = 0; j < 4; j++) {
            const int n0 = bn + wn * 32 + j * 8 + ec;
            const float bn0 = bias_n ? bias_n[n0] : 0.f;
            const float bn1 = bias_n ? bias_n[n0 + 1] : 0.f;
            const float* a = acc[i][j];
            float o00 = (a[0] + bm0 + bn0) * alpha;
            float o01 = (a[1] + bm0 + bn1) * alpha;
            float o10 = (a[2] + bm1 + bn0) * alpha;
            float o11 = (a[3] + bm1 + bn1) * alpha;
            const size_t off0 = (size_t)m0 * ldc + n0;
            const size_t off1 = off0 + (size_t)8 * ldc;
            if (outF) {
                if (resid) {
                    o00 += resid[off0]; o01 += resid[off0 + 1];
                    o10 += resid[off1]; o11 += resid[off1 + 1];
                }
                *(float2*)(outF + off0) = make_float2(o00, o01);
                *(float2*)(outF + off1) = make_float2(o10, o11);
            } else {
                bf16 h0, l0, h1, l1;
                split2(o00, h0, l0); split2(o01, h1, l1);
                *(__nv_bfloat162*)(Chi + off0) = __halves2bfloat162(h0, h1);
                *(__nv_bfloat162*)(Clo + off0) = __halves2bfloat162(l0, l1);
                split2(o10, h0, l0); split2(o11, h1, l1);
                *(__nv_bfloat162*)(Chi + off1) = __halves2bfloat162(h0, h1);
                *(__nv_bfloat162*)(Clo + off1) = __halves2bfloat162(l0, l1);
            }
        }
    }
}

// ---------------------------------------------------------------------------
// Row softmax over 4096-length rows; fp32 in, bf16 hi/lo out. grid=8192, 256 thr.
// ---------------------------------------------------------------------------
__global__ void softmax_split(const float* __restrict__ S,
                              bf16* __restrict__ Ph, bf16* __restrict__ Pl)
{
    const size_t base = (size_t)blockIdx.x * 4096;
    const float4* row = (const float4*)(S + base);
    const int tid = threadIdx.x;
    float4 v[4];
    float mx = -1e30f;
    #pragma unroll
    for (int i = 0; i < 4; i++) {
        v[i] = row[i * 256 + tid];
        mx = fmaxf(mx, fmaxf(fmaxf(v[i].x, v[i].y), fmaxf(v[i].z, v[i].w)));
    }
    __shared__ float red[8];
    #pragma unroll
    for (int o = 16; o > 0; o >>= 1) mx = fmaxf(mx, __shfl_xor_sync(0xffffffffu, mx, o));
    if ((tid & 31) == 0) red[tid >> 5] = mx;
    __syncthreads();
    mx = red[0];
    #pragma unroll
    for (int w = 1; w < 8; w++) mx = fmaxf(mx, red[w]);

    float sum = 0.f;
    #pragma unroll
    for (int i = 0; i < 4; i++) {
        v[i].x = __expf(v[i].x - mx); v[i].y = __expf(v[i].y - mx);
        v[i].z = __expf(v[i].z - mx); v[i].w = __expf(v[i].w - mx);
        sum += v[i].x + v[i].y + v[i].z + v[i].w;
    }
    __syncthreads();
    #pragma unroll
    for (int o = 16; o > 0; o >>= 1) sum += __shfl_xor_sync(0xffffffffu, sum, o);
    if ((tid & 31) == 0) red[tid >> 5] = sum;
    __syncthreads();
    sum = 0.f;
    #pragma unroll
    for (int w = 0; w < 8; w++) sum += red[w];
    const float inv = __frcp_rn(sum);

    #pragma unroll
    for (int i = 0; i < 4; i++) {
        float p[4] = { v[i].x * inv, v[i].y * inv, v[i].z * inv, v[i].w * inv };
        bf16 h[4], l[4];
        #pragma unroll
        for (int j = 0; j < 4; j++) split2(p[j], h[j], l[j]);
        const size_t eoff = base + ((size_t)(i * 256 + tid)) * 4;
        __nv_bfloat162* ph2 = (__nv_bfloat162*)(Ph + eoff);
        __nv_bfloat162* pl2 = (__nv_bfloat162*)(Pl + eoff);
        ph2[0] = __halves2bfloat162(h[0], h[1]);
        ph2[1] = __halves2bfloat162(h[2], h[3]);
        pl2[0] = __halves2bfloat162(l[0], l[1]);
        pl2[1] = __halves2bfloat162(l[2], l[3]);
    }
}

// ---------------------------------------------------------------------------
extern "C" void kernel_launch(void* const* d_in, const int* in_sizes, int n_in,
                              void* d_out, int out_size)
{
    const float* x   = (const float*)d_in[0];
    const float* gnw = (const float*)d_in[1];
    const float* gnb = (const float*)d_in[2];
    const float* qw  = (const float*)d_in[3];
    const float* qb  = (const float*)d_in[4];
    const float* kw  = (const float*)d_in[5];
    const float* kb  = (const float*)d_in[6];
    const float* vw  = (const float*)d_in[7];
    const float* vb  = (const float*)d_in[8];
    const float* pw  = (const float*)d_in[9];
    const float* pb  = (const float*)d_in[10];
    float* out = (float*)d_out;

    bf16 *hh,*hl,*qh,*ql,*kh,*kl,*vth,*vtl,*ah,*al;
    bf16 *wqh,*wql,*wkh,*wkl,*wvh,*wvl,*wph,*wpl, *phh,*pll;
    float *sc;
    cudaGetSymbolAddress((void**)&hh,  g_hh);  cudaGetSymbolAddress((void**)&hl,  g_hl);
    cudaGetSymbolAddress((void**)&qh,  g_qh);  cudaGetSymbolAddress((void**)&ql,  g_ql);
    cudaGetSymbolAddress((void**)&kh,  g_kh);  cudaGetSymbolAddress((void**)&kl,  g_kl);
    cudaGetSymbolAddress((void**)&vth, g_vth); cudaGetSymbolAddress((void**)&vtl, g_vtl);
    cudaGetSymbolAddress((void**)&ah,  g_ah);  cudaGetSymbolAddress((void**)&al,  g_al);
    cudaGetSymbolAddress((void**)&wqh, g_wqh); cudaGetSymbolAddress((void**)&wql, g_wql);
    cudaGetSymbolAddress((void**)&wkh, g_wkh); cudaGetSymbolAddress((void**)&wkl, g_wkl);
    cudaGetSymbolAddress((void**)&wvh, g_wvh); cudaGetSymbolAddress((void**)&wvl, g_wvl);
    cudaGetSymbolAddress((void**)&wph, g_wph); cudaGetSymbolAddress((void**)&wpl, g_wpl);
    cudaGetSymbolAddress((void**)&phh, g_ph);  cudaGetSymbolAddress((void**)&pll, g_pl);
    cudaGetSymbolAddress((void**)&sc,  g_sc);

    cudaFuncSetAttribute(tgemm, cudaFuncAttributeMaxDynamicSharedMemorySize, TG_SMEM);

    const int NW = C_DIM * C_DIM;     // 262144
    const float scale = 0.044194173824159216f;  // 1/sqrt(512)

    // 1. prep: groupnorm+split, weight splits
    gn_transpose<<<64, 256>>>(x, gnw, gnb, hh, hl);
    split_arr<<<NW/256, 256>>>(qw, wqh, wql, NW);
    split_arr<<<NW/256, 256>>>(kw, wkh, wkl, NW);
    split_arr<<<NW/256, 256>>>(vw, wvh, wvl, NW);
    split_arr<<<NW/256, 256>>>(pw, wph, wpl, NW);

    // 2. q = (h @ qw^T + qb) * scale ; k = h @ kw^T + kb   (token-major, split out)
    tgemm<<<dim3(4, 64), 256, TG_SMEM>>>(hh, hl, 512, wqh, wql, 512, 512, scale,
                                         nullptr, qb, nullptr, nullptr, qh, ql, 512);
    tgemm<<<dim3(4, 64), 256, TG_SMEM>>>(hh, hl, 512, wkh, wkl, 512, 512, 1.f,
                                         nullptr, kb, nullptr, nullptr, kh, kl, 512);
    // 3. vt = vw @ h^T + vb    (channel-major, ld 8192, split out)
    tgemm<<<dim3(64, 4), 256, TG_SMEM>>>(wvh, wvl, 512, hh, hl, 512, 512, 1.f,
                                         vb, nullptr, nullptr, nullptr, vth, vtl, 8192);

    // 4. scores[b] = q_b @ k_b^T   (fp32 out; scale already folded into q)
    for (int b = 0; b < 2; b++) {
        tgemm<<<dim3(32, 32), 256, TG_SMEM>>>(
            qh + (size_t)b*HW*C_DIM, ql + (size_t)b*HW*C_DIM, 512,
            kh + (size_t)b*HW*C_DIM, kl + (size_t)b*HW*C_DIM, 512,
            512, 1.f, nullptr, nullptr, nullptr,
            sc + (size_t)b*HW*HW, nullptr, nullptr, 4096);
    }
    // 5. softmax -> split probs
    softmax_split<<<8192, 256>>>(sc, phh, pll);

    // 6. att[b] = P_b @ V_b   (split out, token-major)
    for (int b = 0; b < 2; b++) {
        tgemm<<<dim3(4, 32), 256, TG_SMEM>>>(
            phh + (size_t)b*HW*HW, pll + (size_t)b*HW*HW, 4096,
            vth + (size_t)b*HW,    vtl + (size_t)b*HW,    8192,
            4096, 1.f, nullptr, nullptr, nullptr,
            nullptr, ah + (size_t)b*HW*C_DIM, al + (size_t)b*HW*C_DIM, 512);
    }
    // 7. out[b] = pw @ att_b^T + pb + x_b   (fp32, directly in (B,C,H,W))
    for (int b = 0; b < 2; b++) {
        tgemm<<<dim3(32, 4), 256, TG_SMEM>>>(
            wph, wpl, 512,
            ah + (size_t)b*HW*C_DIM, al + (size_t)b*HW*C_DIM, 512,
            512, 1.f, pb, nullptr, x + (size_t)b*C_DIM*HW,
            out + (size_t)b*C_DIM*HW, nullptr, nullptr, 4096);
    }
}